// round 12
// baseline (speedup 1.0000x reference)
#include <cuda_runtime.h>
#include <cstdint>

#define NH 8
#define HD 48
#define CC 384
#define NN 1024
#define BB 16

// Scratch (device globals; no allocations allowed)
__device__ float g_q[BB*NH*NN*HD];
__device__ float g_k[BB*NH*NN*HD];
__device__ float g_v[BB*NH*NN*HD];
__device__ float g_o[BB*NN*CC];

// ---------------------------------------------------------------------------
// tf32 helpers (sm_80+ baseline ISA)
// ---------------------------------------------------------------------------
__device__ __forceinline__ float tf32r(float x) {
    uint32_t r;
    asm("cvt.rna.tf32.f32 %0, %1;" : "=r"(r) : "f"(x));
    return __uint_as_float(r);
}
__device__ __forceinline__ void mma_tf32(float* acc, const float* a, float b0, float b1) {
    asm volatile(
        "mma.sync.aligned.m16n8k8.row.col.f32.tf32.tf32.f32 "
        "{%0,%1,%2,%3}, {%4,%5,%6,%7}, {%8,%9}, {%0,%1,%2,%3};"
        : "+f"(acc[0]), "+f"(acc[1]), "+f"(acc[2]), "+f"(acc[3])
        : "r"(__float_as_uint(a[0])), "r"(__float_as_uint(a[1])),
          "r"(__float_as_uint(a[2])), "r"(__float_as_uint(a[3])),
          "r"(__float_as_uint(b0)),  "r"(__float_as_uint(b1)));
}

// ===========================================================================
// GEMM 1 (tf32 TC, transpose-free): C[j][n] = sum_k w[j][k] * x[b][k][n]
// R12: register prefetch of next K-step (proj-style pipeline).
// ===========================================================================
__global__ __launch_bounds__(256) void gemm_qkv_tc(const float* __restrict__ x,
                                                   const float* __restrict__ w,
                                                   const float* __restrict__ bias) {
    __shared__ float As[128 * 36];   // [j][k]
    __shared__ float Bs[32 * 136];   // [k][n]
    const int b  = blockIdx.z;
    const int j0 = blockIdx.x * 128;
    const int n0 = blockIdx.y * 128;
    const int t  = threadIdx.x;
    const int w8 = t >> 5, lane = t & 31;
    const int lr = lane >> 2, lc = lane & 3;
    const int wm = w8 & 1, wn = w8 >> 1;

    float acc[4][4][4];
#pragma unroll
    for (int i = 0; i < 4; ++i)
#pragma unroll
        for (int j = 0; j < 4; ++j)
#pragma unroll
            for (int e = 0; e < 4; ++e) acc[i][j][e] = 0.f;

    const float* xb = x + (size_t)b * CC * NN;

    float4 apre[4], bpre[4];
#pragma unroll
    for (int r = 0; r < 4; ++r) {
        int idx = t + r * 256;
        int j = idx >> 3, k4 = idx & 7;
        apre[r] = *(const float4*)(w + (size_t)(j0 + j) * CC + k4 * 4);
        int kk = idx >> 5, m4 = idx & 31;
        bpre[r] = *(const float4*)(xb + (size_t)kk * NN + n0 + m4 * 4);
    }

    for (int k0 = 0; k0 < CC; k0 += 32) {
        __syncthreads();
#pragma unroll
        for (int r = 0; r < 4; ++r) {
            int idx = t + r * 256;
            int j = idx >> 3, k4 = idx & 7;
            float4 v = apre[r];
            v.x = tf32r(v.x); v.y = tf32r(v.y); v.z = tf32r(v.z); v.w = tf32r(v.w);
            *(float4*)&As[j * 36 + k4 * 4] = v;
            int kk = idx >> 5, m4 = idx & 31;
            float4 u = bpre[r];
            u.x = tf32r(u.x); u.y = tf32r(u.y); u.z = tf32r(u.z); u.w = tf32r(u.w);
            *(float4*)&Bs[kk * 136 + m4 * 4] = u;
        }
        if (k0 + 32 < CC) {
            const int k1 = k0 + 32;
#pragma unroll
            for (int r = 0; r < 4; ++r) {
                int idx = t + r * 256;
                int j = idx >> 3, k4 = idx & 7;
                apre[r] = *(const float4*)(w + (size_t)(j0 + j) * CC + k1 + k4 * 4);
                int kk = idx >> 5, m4 = idx & 31;
                bpre[r] = *(const float4*)(xb + (size_t)(k1 + kk) * NN + n0 + m4 * 4);
            }
        }
        __syncthreads();
#pragma unroll
        for (int kb = 0; kb < 4; ++kb) {
            float af[4][4], bf[4][2];
#pragma unroll
            for (int mt = 0; mt < 4; ++mt) {
                int base = (wm * 64 + mt * 16 + lr) * 36 + kb * 8 + lc;
                af[mt][0] = As[base];
                af[mt][1] = As[base + 8 * 36];
                af[mt][2] = As[base + 4];
                af[mt][3] = As[base + 8 * 36 + 4];
            }
#pragma unroll
            for (int nb = 0; nb < 4; ++nb) {
                int nn = wn * 32 + nb * 8 + lr;
                bf[nb][0] = Bs[(kb * 8 + lc) * 136 + nn];
                bf[nb][1] = Bs[(kb * 8 + lc + 4) * 136 + nn];
            }
#pragma unroll
            for (int mt = 0; mt < 4; ++mt)
#pragma unroll
                for (int nb = 0; nb < 4; ++nb)
                    mma_tf32(acc[mt][nb], af[mt], bf[nb][0], bf[nb][1]);
        }
    }

    const int which = j0 / CC;
    float* dst = (which == 0) ? g_q : (which == 1) ? g_k : g_v;
#pragma unroll
    for (int mt = 0; mt < 4; ++mt) {
        int j1 = j0 + wm * 64 + mt * 16 + lr;
        int j2 = j1 + 8;
        int rem1 = j1 - which * CC;
        int h1 = rem1 / HD, d1 = rem1 - h1 * HD;
        int rem2 = j2 - which * CC;
        int h2 = rem2 / HD, d2 = rem2 - h2 * HD;
        float bj1 = bias[j1], bj2 = bias[j2];
        size_t base1 = ((size_t)b * NH + h1) * NN;
        size_t base2 = ((size_t)b * NH + h2) * NN;
#pragma unroll
        for (int nb = 0; nb < 4; ++nb) {
            int n = n0 + wn * 32 + nb * 8 + 2 * lc;
            dst[(base1 + n)     * HD + d1] = acc[mt][nb][0] + bj1;
            dst[(base1 + n + 1) * HD + d1] = acc[mt][nb][1] + bj1;
            dst[(base2 + n)     * HD + d2] = acc[mt][nb][2] + bj2;
            dst[(base2 + n + 1) * HD + d2] = acc[mt][nb][3] + bj2;
        }
    }
}

// ---------------------------------------------------------------------------
// Tensor-core flash attention, tf32 mma.sync.
// R12: l2-normalization FUSED into Q and K loaders (l2norm kernel deleted).
// Loader mapping: 4 threads per row; thread owns 12 contiguous elements
// (3 float4); sum-of-squares reduced with 2 quad shfls; fp32 normalize then
// tf32 round — bit-identical to the old standalone l2norm + attn path.
// ---------------------------------------------------------------------------
#define KS_STRIDE 52
#define VS_STRIDE 72
#define PS_STRIDE 68
#define SM_VS_F   (64 * KS_STRIDE)
#define SM_PS_F   (SM_VS_F + 64 * VS_STRIDE)
#define ATTN_SMEM_F (SM_PS_F + 8 * 16 * PS_STRIDE)

__global__ __launch_bounds__(256, 2) void attn_mma(const float* __restrict__ temp) {
    extern __shared__ float sm[];
    float* Ks = sm;
    float* Vs = sm + SM_VS_F;
    float* Ps = sm + SM_PS_F;

    const int t = threadIdx.x;
    const int w = t >> 5;
    const int lane = t & 31;
    const int lr = lane >> 2;
    const int lc = lane & 3;
    const int rql = t >> 2;      // row (0..63) for 4-threads-per-row loaders
    const int sq  = t & 3;       // quad slot; owns elements sq*12 .. sq*12+11
    const int i0 = blockIdx.x * 128;
    const int bh = blockIdx.y;
    const int h  = bh & (NH - 1);
    const float* qg = g_q + (size_t)bh * NN * HD;
    const float* kg = g_k + (size_t)bh * NN * HD;
    const float* vg = g_v + (size_t)bh * NN * HD;
    const float tpr = temp[h];
    const float mterm = fabsf(tpr);

    // stage Q (raw) with fused l2norm, via Ks region
#pragma unroll
    for (int it = 0; it < 2; ++it) {
        int r = it * 64 + rql;
        const float* qp = qg + (size_t)(i0 + r) * HD + sq * 12;
        float4 v0 = *(const float4*)(qp);
        float4 v1 = *(const float4*)(qp + 4);
        float4 v2 = *(const float4*)(qp + 8);
        float ss = v0.x*v0.x + v0.y*v0.y + v0.z*v0.z + v0.w*v0.w
                 + v1.x*v1.x + v1.y*v1.y + v1.z*v1.z + v1.w*v1.w
                 + v2.x*v2.x + v2.y*v2.y + v2.z*v2.z + v2.w*v2.w;
        ss += __shfl_xor_sync(0xffffffffu, ss, 1);
        ss += __shfl_xor_sync(0xffffffffu, ss, 2);
        float inv = 1.0f / fmaxf(sqrtf(ss), 1e-12f);
        float* d = &sm[r * KS_STRIDE + sq * 12];
        d[0] = tf32r(v0.x*inv); d[1] = tf32r(v0.y*inv); d[2]  = tf32r(v0.z*inv); d[3]  = tf32r(v0.w*inv);
        d[4] = tf32r(v1.x*inv); d[5] = tf32r(v1.y*inv); d[6]  = tf32r(v1.z*inv); d[7]  = tf32r(v1.w*inv);
        d[8] = tf32r(v2.x*inv); d[9] = tf32r(v2.y*inv); d[10] = tf32r(v2.z*inv); d[11] = tf32r(v2.w*inv);
    }
    __syncthreads();

    float qf[6][4];
    {
        const int mr = w * 16 + lr;
#pragma unroll
        for (int kb = 0; kb < 6; ++kb) {
            qf[kb][0] = sm[mr * KS_STRIDE + kb * 8 + lc];
            qf[kb][1] = sm[(mr + 8) * KS_STRIDE + kb * 8 + lc];
            qf[kb][2] = sm[mr * KS_STRIDE + kb * 8 + lc + 4];
            qf[kb][3] = sm[(mr + 8) * KS_STRIDE + kb * 8 + lc + 4];
        }
    }

    float oacc[6][4];
#pragma unroll
    for (int i = 0; i < 6; ++i)
#pragma unroll
        for (int j = 0; j < 4; ++j) oacc[i][j] = 0.f;
    float rsum0 = 0.f, rsum1 = 0.f;
    float* Pw = Ps + w * 16 * PS_STRIDE;

    // prefetch tile 0 (K row rql, V row rql; elements sq*12..)
    float4 kpre[3], vpre[3];
    {
        const float* kp = kg + (size_t)rql * HD + sq * 12;
        const float* vp = vg + (size_t)rql * HD + sq * 12;
        kpre[0] = *(const float4*)(kp);     vpre[0] = *(const float4*)(vp);
        kpre[1] = *(const float4*)(kp + 4); vpre[1] = *(const float4*)(vp + 4);
        kpre[2] = *(const float4*)(kp + 8); vpre[2] = *(const float4*)(vp + 8);
    }

    for (int kt = 0; kt < 16; ++kt) {
        __syncthreads();   // prior compute done
        // K: fused l2norm + tf32 round; V: tf32 round only
        {
            float ss = kpre[0].x*kpre[0].x + kpre[0].y*kpre[0].y + kpre[0].z*kpre[0].z + kpre[0].w*kpre[0].w
                     + kpre[1].x*kpre[1].x + kpre[1].y*kpre[1].y + kpre[1].z*kpre[1].z + kpre[1].w*kpre[1].w
                     + kpre[2].x*kpre[2].x + kpre[2].y*kpre[2].y + kpre[2].z*kpre[2].z + kpre[2].w*kpre[2].w;
            ss += __shfl_xor_sync(0xffffffffu, ss, 1);
            ss += __shfl_xor_sync(0xffffffffu, ss, 2);
            float inv = 1.0f / fmaxf(sqrtf(ss), 1e-12f);
            float* dk = &Ks[rql * KS_STRIDE + sq * 12];
            dk[0] = tf32r(kpre[0].x*inv); dk[1] = tf32r(kpre[0].y*inv); dk[2]  = tf32r(kpre[0].z*inv); dk[3]  = tf32r(kpre[0].w*inv);
            dk[4] = tf32r(kpre[1].x*inv); dk[5] = tf32r(kpre[1].y*inv); dk[6]  = tf32r(kpre[1].z*inv); dk[7]  = tf32r(kpre[1].w*inv);
            dk[8] = tf32r(kpre[2].x*inv); dk[9] = tf32r(kpre[2].y*inv); dk[10] = tf32r(kpre[2].z*inv); dk[11] = tf32r(kpre[2].w*inv);
            float* dv = &Vs[rql * VS_STRIDE + sq * 12];
            dv[0] = tf32r(vpre[0].x); dv[1] = tf32r(vpre[0].y); dv[2]  = tf32r(vpre[0].z); dv[3]  = tf32r(vpre[0].w);
            dv[4] = tf32r(vpre[1].x); dv[5] = tf32r(vpre[1].y); dv[6]  = tf32r(vpre[1].z); dv[7]  = tf32r(vpre[1].w);
            dv[8] = tf32r(vpre[2].x); dv[9] = tf32r(vpre[2].y); dv[10] = tf32r(vpre[2].z); dv[11] = tf32r(vpre[2].w);
        }
        // issue next tile's loads; they complete under the mma phase
        if (kt < 15) {
            const int k1 = (kt + 1) * 64;
            const float* kp = kg + (size_t)(k1 + rql) * HD + sq * 12;
            const float* vp = vg + (size_t)(k1 + rql) * HD + sq * 12;
            kpre[0] = *(const float4*)(kp);     vpre[0] = *(const float4*)(vp);
            kpre[1] = *(const float4*)(kp + 4); vpre[1] = *(const float4*)(vp + 4);
            kpre[2] = *(const float4*)(kp + 8); vpre[2] = *(const float4*)(vp + 8);
        }
        __syncthreads();

        // ---- S = Q.K^T + softmax, two halves of 4 n-blocks ----
#pragma unroll
        for (int half = 0; half < 2; ++half) {
            float sacc[4][4];
#pragma unroll
            for (int i = 0; i < 4; ++i)
#pragma unroll
                for (int j = 0; j < 4; ++j) sacc[i][j] = 0.f;
#pragma unroll
            for (int nb4 = 0; nb4 < 4; ++nb4) {
                const int nb = half * 4 + nb4;
                const float* kbase = Ks + (nb * 8 + lr) * KS_STRIDE + lc;
#pragma unroll
                for (int kb = 0; kb < 6; ++kb) {
                    float b0 = kbase[kb * 8];
                    float b1 = kbase[kb * 8 + 4];
                    mma_tf32(sacc[nb4], qf[kb], b0, b1);
                }
            }
#pragma unroll
            for (int nb4 = 0; nb4 < 4; ++nb4) {
                const int nb = half * 4 + nb4;
                float p0 = __expf(fmaf(sacc[nb4][0], tpr, -mterm));
                float p1 = __expf(fmaf(sacc[nb4][1], tpr, -mterm));
                float p2 = __expf(fmaf(sacc[nb4][2], tpr, -mterm));
                float p3 = __expf(fmaf(sacc[nb4][3], tpr, -mterm));
                rsum0 += p0 + p1;
                rsum1 += p2 + p3;
                *(float2*)&Pw[lr * PS_STRIDE + nb * 8 + 2 * lc] =
                    make_float2(tf32r(p0), tf32r(p1));
                *(float2*)&Pw[(lr + 8) * PS_STRIDE + nb * 8 + 2 * lc] =
                    make_float2(tf32r(p2), tf32r(p3));
            }
        }
        __syncwarp();

        // ---- O += P.V ----
#pragma unroll
        for (int kb2 = 0; kb2 < 8; ++kb2) {
            float af[4];
            af[0] = Pw[lr * PS_STRIDE + kb2 * 8 + lc];
            af[1] = Pw[(lr + 8) * PS_STRIDE + kb2 * 8 + lc];
            af[2] = Pw[lr * PS_STRIDE + kb2 * 8 + lc + 4];
            af[3] = Pw[(lr + 8) * PS_STRIDE + kb2 * 8 + lc + 4];
            const float* vb0 = Vs + (kb2 * 8 + lc) * VS_STRIDE + lr;
            const float* vb1 = Vs + (kb2 * 8 + lc + 4) * VS_STRIDE + lr;
#pragma unroll
            for (int nb2 = 0; nb2 < 6; ++nb2) {
                mma_tf32(oacc[nb2], af, vb0[nb2 * 8], vb1[nb2 * 8]);
            }
        }
    }

    rsum0 += __shfl_xor_sync(0xffffffffu, rsum0, 1);
    rsum0 += __shfl_xor_sync(0xffffffffu, rsum0, 2);
    rsum1 += __shfl_xor_sync(0xffffffffu, rsum1, 1);
    rsum1 += __shfl_xor_sync(0xffffffffu, rsum1, 2);
    const float inv0 = 1.0f / rsum0;
    const float inv1 = 1.0f / rsum1;
    const int b = bh >> 3;
    const int row0 = i0 + w * 16 + lr;
    float* o0 = g_o + ((size_t)b * NN + row0) * CC + h * HD;
    float* o1 = o0 + 8 * CC;
#pragma unroll
    for (int nb = 0; nb < 6; ++nb) {
        *(float2*)&o0[nb * 8 + 2 * lc] = make_float2(oacc[nb][0] * inv0, oacc[nb][1] * inv0);
        *(float2*)&o1[nb * 8 + 2 * lc] = make_float2(oacc[nb][2] * inv1, oacc[nb][3] * inv1);
    }
}

// ===========================================================================
// GEMM 2 (tf32 TC): out[b,j,n] = sum_c g_o[b,n,c]*proj_w[j,c]+pb[j]
// R11 structure + __launch_bounds__(256,2) for 2 CTAs/SM.
// ===========================================================================
__global__ __launch_bounds__(256, 2) void gemm_proj_tc(const float* __restrict__ w,
                                                       const float* __restrict__ bias,
                                                       float* __restrict__ out) {
    __shared__ float Sm[9216];
    float* As = Sm;               // [m][k] 128x36
    float* Bs = Sm + 128 * 36;    // [j][k] 128x36
    float* Cs = Sm;               // [j][m] 64x132 per pass

    const int b  = blockIdx.z;
    const int m0 = blockIdx.y * 128;
    const int j0 = blockIdx.x * 128;
    const int t  = threadIdx.x;
    const int w8 = t >> 5, lane = t & 31;
    const int lr = lane >> 2, lc = lane & 3;
    const int wm = w8 & 1, wn = w8 >> 1;

    float acc[4][4][4];
#pragma unroll
    for (int i = 0; i < 4; ++i)
#pragma unroll
        for (int j = 0; j < 4; ++j)
#pragma unroll
            for (int e = 0; e < 4; ++e) acc[i][j][e] = 0.f;

    const float* A = g_o + (size_t)b * NN * CC;

    float4 apre[4], bpre[4];
#pragma unroll
    for (int r = 0; r < 4; ++r) {
        int idx = t + r * 256;
        int m = idx >> 3, k4 = idx & 7;
        apre[r] = *(const float4*)(A + (size_t)(m0 + m) * CC + k4 * 4);
        bpre[r] = *(const float4*)(w + (size_t)(j0 + m) * CC + k4 * 4);
    }

    for (int k0 = 0; k0 < CC; k0 += 32) {
        __syncthreads();
#pragma unroll
        for (int r = 0; r < 4; ++r) {
            int idx = t + r * 256;
            int m = idx >> 3, k4 = idx & 7;
            float4 v = apre[r];
            v.x = tf32r(v.x); v.y = tf32r(v.y); v.z = tf32r(v.z); v.w = tf32r(v.w);
            *(float4*)&As[m * 36 + k4 * 4] = v;
            float4 u = bpre[r];
            u.x = tf32r(u.x); u.y = tf32r(u.y); u.z = tf32r(u.z); u.w = tf32r(u.w);
            *(float4*)&Bs[m * 36 + k4 * 4] = u;
        }
        if (k0 + 32 < CC) {
            const int k1 = k0 + 32;
#pragma unroll
            for (int r = 0; r < 4; ++r) {
                int idx = t + r * 256;
                int m = idx >> 3, k4 = idx & 7;
                apre[r] = *(const float4*)(A + (size_t)(m0 + m) * CC + k1 + k4 * 4);
                bpre[r] = *(const float4*)(w + (size_t)(j0 + m) * CC + k1 + k4 * 4);
            }
        }
        __syncthreads();
#pragma unroll
        for (int kb = 0; kb < 4; ++kb) {
            float af[4][4], bf[4][2];
#pragma unroll
            for (int mt = 0; mt < 4; ++mt) {
                int base = (wm * 64 + mt * 16 + lr) * 36 + kb * 8 + lc;
                af[mt][0] = As[base];
                af[mt][1] = As[base + 8 * 36];
                af[mt][2] = As[base + 4];
                af[mt][3] = As[base + 8 * 36 + 4];
            }
#pragma unroll
            for (int nb = 0; nb < 4; ++nb) {
                int bb = (wn * 32 + nb * 8 + lr) * 36 + kb * 8 + lc;
                bf[nb][0] = Bs[bb];
                bf[nb][1] = Bs[bb + 4];
            }
#pragma unroll
            for (int mt = 0; mt < 4; ++mt)
#pragma unroll
                for (int nb = 0; nb < 4; ++nb)
                    mma_tf32(acc[mt][nb], af[mt], bf[nb][0], bf[nb][1]);
        }
    }

    // 2-pass epilogue: stage C[j][m] -> coalesced store along n
#pragma unroll
    for (int hh = 0; hh < 2; ++hh) {
        __syncthreads();
        if ((wn >> 1) == hh) {
#pragma unroll
            for (int mt = 0; mt < 4; ++mt) {
                int m1 = wm * 64 + mt * 16 + lr;
                int m2 = m1 + 8;
#pragma unroll
                for (int nb = 0; nb < 4; ++nb) {
                    int jl = (wn & 1) * 32 + nb * 8 + 2 * lc;
                    Cs[jl * 132 + m1]       = acc[mt][nb][0];
                    Cs[(jl + 1) * 132 + m1] = acc[mt][nb][1];
                    Cs[jl * 132 + m2]       = acc[mt][nb][2];
                    Cs[(jl + 1) * 132 + m2] = acc[mt][nb][3];
                }
            }
        }
        __syncthreads();
#pragma unroll
        for (int r = 0; r < 8; ++r) {
            int idx = t + r * 256;
            int jl = idx >> 5, m4 = idx & 31;
            int jg = j0 + hh * 64 + jl;
            float bj = bias[jg];
            float4 v = *(float4*)&Cs[jl * 132 + m4 * 4];
            v.x += bj; v.y += bj; v.z += bj; v.w += bj;
            *(float4*)(out + ((size_t)b * CC + jg) * NN + m0 + m4 * 4) = v;
        }
    }
}

// ===========================================================================
extern "C" void kernel_launch(void* const* d_in, const int* in_sizes, int n_in,
                              void* d_out, int out_size) {
    const float* x      = (const float*)d_in[0];
    const float* temp   = (const float*)d_in[1];
    const float* qkv_w  = (const float*)d_in[2];
    const float* qkv_b  = (const float*)d_in[3];
    const float* proj_w = (const float*)d_in[4];
    const float* proj_b = (const float*)d_in[5];
    float* out = (float*)d_out;

    static const int ATTN_SMEM = ATTN_SMEM_F * 4;   // 66560 bytes
    cudaFuncSetAttribute(attn_mma, cudaFuncAttributeMaxDynamicSharedMemorySize,
                         ATTN_SMEM);

    gemm_qkv_tc<<<dim3(9, 8, BB), 256>>>(x, qkv_w, qkv_b);
    attn_mma<<<dim3(8, BB * NH), 256, ATTN_SMEM>>>(temp);
    gemm_proj_tc<<<dim3(3, 8, BB), 256>>>(proj_w, proj_b, out);
}

// round 13
// speedup vs baseline: 1.0486x; 1.0486x over previous
#include <cuda_runtime.h>
#include <cstdint>

#define NH 8
#define HD 48
#define CC 384
#define NN 1024
#define BB 16

// Scratch (device globals; no allocations allowed)
__device__ float g_q[BB*NH*NN*HD];
__device__ float g_k[BB*NH*NN*HD];
__device__ float g_v[BB*NH*NN*HD];
__device__ float g_o[BB*NN*CC];

// ---------------------------------------------------------------------------
// tf32 helpers (sm_80+ baseline ISA)
// ---------------------------------------------------------------------------
__device__ __forceinline__ float tf32r(float x) {
    uint32_t r;
    asm("cvt.rna.tf32.f32 %0, %1;" : "=r"(r) : "f"(x));
    return __uint_as_float(r);
}
__device__ __forceinline__ void mma_tf32(float* acc, const float* a, float b0, float b1) {
    asm volatile(
        "mma.sync.aligned.m16n8k8.row.col.f32.tf32.tf32.f32 "
        "{%0,%1,%2,%3}, {%4,%5,%6,%7}, {%8,%9}, {%0,%1,%2,%3};"
        : "+f"(acc[0]), "+f"(acc[1]), "+f"(acc[2]), "+f"(acc[3])
        : "r"(__float_as_uint(a[0])), "r"(__float_as_uint(a[1])),
          "r"(__float_as_uint(a[2])), "r"(__float_as_uint(a[3])),
          "r"(__float_as_uint(b0)),  "r"(__float_as_uint(b1)));
}

// ===========================================================================
// GEMM 1 (tf32 TC, transpose-free): C[j][n] = sum_k w[j][k] * x[b][k][n]
// EXACT R10 version (87us) — no register prefetch (it cost occupancy: R12
// showed regs 126->170, occ 12.3%, dur 126us).
// ===========================================================================
__global__ __launch_bounds__(256) void gemm_qkv_tc(const float* __restrict__ x,
                                                   const float* __restrict__ w,
                                                   const float* __restrict__ bias) {
    __shared__ float As[128 * 36];   // [j][k]
    __shared__ float Bs[32 * 136];   // [k][n]
    const int b  = blockIdx.z;
    const int j0 = blockIdx.x * 128;
    const int n0 = blockIdx.y * 128;
    const int t  = threadIdx.x;
    const int w8 = t >> 5, lane = t & 31;
    const int lr = lane >> 2, lc = lane & 3;
    const int wm = w8 & 1, wn = w8 >> 1;

    float acc[4][4][4];
#pragma unroll
    for (int i = 0; i < 4; ++i)
#pragma unroll
        for (int j = 0; j < 4; ++j)
#pragma unroll
            for (int e = 0; e < 4; ++e) acc[i][j][e] = 0.f;

    const float* xb = x + (size_t)b * CC * NN;

    for (int k0 = 0; k0 < CC; k0 += 32) {
        __syncthreads();
#pragma unroll
        for (int r = 0; r < 4; ++r) {
            int idx = t + r * 256;
            int j = idx >> 3, k4 = idx & 7;
            float4 v = *(const float4*)(w + (size_t)(j0 + j) * CC + k0 + k4 * 4);
            v.x = tf32r(v.x); v.y = tf32r(v.y); v.z = tf32r(v.z); v.w = tf32r(v.w);
            *(float4*)&As[j * 36 + k4 * 4] = v;
        }
#pragma unroll
        for (int r = 0; r < 4; ++r) {
            int idx = t + r * 256;
            int kk = idx >> 5, m4 = idx & 31;
            float4 v = *(const float4*)(xb + (size_t)(k0 + kk) * NN + n0 + m4 * 4);
            v.x = tf32r(v.x); v.y = tf32r(v.y); v.z = tf32r(v.z); v.w = tf32r(v.w);
            *(float4*)&Bs[kk * 136 + m4 * 4] = v;
        }
        __syncthreads();
#pragma unroll
        for (int kb = 0; kb < 4; ++kb) {
            float af[4][4], bf[4][2];
#pragma unroll
            for (int mt = 0; mt < 4; ++mt) {
                int base = (wm * 64 + mt * 16 + lr) * 36 + kb * 8 + lc;
                af[mt][0] = As[base];
                af[mt][1] = As[base + 8 * 36];
                af[mt][2] = As[base + 4];
                af[mt][3] = As[base + 8 * 36 + 4];
            }
#pragma unroll
            for (int nb = 0; nb < 4; ++nb) {
                int nn = wn * 32 + nb * 8 + lr;
                bf[nb][0] = Bs[(kb * 8 + lc) * 136 + nn];
                bf[nb][1] = Bs[(kb * 8 + lc + 4) * 136 + nn];
            }
#pragma unroll
            for (int mt = 0; mt < 4; ++mt)
#pragma unroll
                for (int nb = 0; nb < 4; ++nb)
                    mma_tf32(acc[mt][nb], af[mt], bf[nb][0], bf[nb][1]);
        }
    }

    const int which = j0 / CC;
    float* dst = (which == 0) ? g_q : (which == 1) ? g_k : g_v;
#pragma unroll
    for (int mt = 0; mt < 4; ++mt) {
        int j1 = j0 + wm * 64 + mt * 16 + lr;
        int j2 = j1 + 8;
        int rem1 = j1 - which * CC;
        int h1 = rem1 / HD, d1 = rem1 - h1 * HD;
        int rem2 = j2 - which * CC;
        int h2 = rem2 / HD, d2 = rem2 - h2 * HD;
        float bj1 = bias[j1], bj2 = bias[j2];
        size_t base1 = ((size_t)b * NH + h1) * NN;
        size_t base2 = ((size_t)b * NH + h2) * NN;
#pragma unroll
        for (int nb = 0; nb < 4; ++nb) {
            int n = n0 + wn * 32 + nb * 8 + 2 * lc;
            dst[(base1 + n)     * HD + d1] = acc[mt][nb][0] + bj1;
            dst[(base1 + n + 1) * HD + d1] = acc[mt][nb][1] + bj1;
            dst[(base2 + n)     * HD + d2] = acc[mt][nb][2] + bj2;
            dst[(base2 + n + 1) * HD + d2] = acc[mt][nb][3] + bj2;
        }
    }
}

// ---------------------------------------------------------------------------
// Tensor-core flash attention, tf32 mma.sync, fused l2norm (R12 version).
// ---------------------------------------------------------------------------
#define KS_STRIDE 52
#define VS_STRIDE 72
#define PS_STRIDE 68
#define SM_VS_F   (64 * KS_STRIDE)
#define SM_PS_F   (SM_VS_F + 64 * VS_STRIDE)
#define ATTN_SMEM_F (SM_PS_F + 8 * 16 * PS_STRIDE)

__global__ __launch_bounds__(256, 2) void attn_mma(const float* __restrict__ temp) {
    extern __shared__ float sm[];
    float* Ks = sm;
    float* Vs = sm + SM_VS_F;
    float* Ps = sm + SM_PS_F;

    const int t = threadIdx.x;
    const int w = t >> 5;
    const int lane = t & 31;
    const int lr = lane >> 2;
    const int lc = lane & 3;
    const int rql = t >> 2;      // row (0..63) for 4-threads-per-row loaders
    const int sq  = t & 3;       // quad slot; owns elements sq*12 .. sq*12+11
    const int i0 = blockIdx.x * 128;
    const int bh = blockIdx.y;
    const int h  = bh & (NH - 1);
    const float* qg = g_q + (size_t)bh * NN * HD;
    const float* kg = g_k + (size_t)bh * NN * HD;
    const float* vg = g_v + (size_t)bh * NN * HD;
    const float tpr = temp[h];
    const float mterm = fabsf(tpr);

    // stage Q (raw) with fused l2norm, via Ks region
#pragma unroll
    for (int it = 0; it < 2; ++it) {
        int r = it * 64 + rql;
        const float* qp = qg + (size_t)(i0 + r) * HD + sq * 12;
        float4 v0 = *(const float4*)(qp);
        float4 v1 = *(const float4*)(qp + 4);
        float4 v2 = *(const float4*)(qp + 8);
        float ss = v0.x*v0.x + v0.y*v0.y + v0.z*v0.z + v0.w*v0.w
                 + v1.x*v1.x + v1.y*v1.y + v1.z*v1.z + v1.w*v1.w
                 + v2.x*v2.x + v2.y*v2.y + v2.z*v2.z + v2.w*v2.w;
        ss += __shfl_xor_sync(0xffffffffu, ss, 1);
        ss += __shfl_xor_sync(0xffffffffu, ss, 2);
        float inv = 1.0f / fmaxf(sqrtf(ss), 1e-12f);
        float* d = &sm[r * KS_STRIDE + sq * 12];
        d[0] = tf32r(v0.x*inv); d[1] = tf32r(v0.y*inv); d[2]  = tf32r(v0.z*inv); d[3]  = tf32r(v0.w*inv);
        d[4] = tf32r(v1.x*inv); d[5] = tf32r(v1.y*inv); d[6]  = tf32r(v1.z*inv); d[7]  = tf32r(v1.w*inv);
        d[8] = tf32r(v2.x*inv); d[9] = tf32r(v2.y*inv); d[10] = tf32r(v2.z*inv); d[11] = tf32r(v2.w*inv);
    }
    __syncthreads();

    float qf[6][4];
    {
        const int mr = w * 16 + lr;
#pragma unroll
        for (int kb = 0; kb < 6; ++kb) {
            qf[kb][0] = sm[mr * KS_STRIDE + kb * 8 + lc];
            qf[kb][1] = sm[(mr + 8) * KS_STRIDE + kb * 8 + lc];
            qf[kb][2] = sm[mr * KS_STRIDE + kb * 8 + lc + 4];
            qf[kb][3] = sm[(mr + 8) * KS_STRIDE + kb * 8 + lc + 4];
        }
    }

    float oacc[6][4];
#pragma unroll
    for (int i = 0; i < 6; ++i)
#pragma unroll
        for (int j = 0; j < 4; ++j) oacc[i][j] = 0.f;
    float rsum0 = 0.f, rsum1 = 0.f;
    float* Pw = Ps + w * 16 * PS_STRIDE;

    // prefetch tile 0 (K row rql, V row rql; elements sq*12..)
    float4 kpre[3], vpre[3];
    {
        const float* kp = kg + (size_t)rql * HD + sq * 12;
        const float* vp = vg + (size_t)rql * HD + sq * 12;
        kpre[0] = *(const float4*)(kp);     vpre[0] = *(const float4*)(vp);
        kpre[1] = *(const float4*)(kp + 4); vpre[1] = *(const float4*)(vp + 4);
        kpre[2] = *(const float4*)(kp + 8); vpre[2] = *(const float4*)(vp + 8);
    }

    for (int kt = 0; kt < 16; ++kt) {
        __syncthreads();   // prior compute done
        // K: fused l2norm + tf32 round; V: tf32 round only
        {
            float ss = kpre[0].x*kpre[0].x + kpre[0].y*kpre[0].y + kpre[0].z*kpre[0].z + kpre[0].w*kpre[0].w
                     + kpre[1].x*kpre[1].x + kpre[1].y*kpre[1].y + kpre[1].z*kpre[1].z + kpre[1].w*kpre[1].w
                     + kpre[2].x*kpre[2].x + kpre[2].y*kpre[2].y + kpre[2].z*kpre[2].z + kpre[2].w*kpre[2].w;
            ss += __shfl_xor_sync(0xffffffffu, ss, 1);
            ss += __shfl_xor_sync(0xffffffffu, ss, 2);
            float inv = 1.0f / fmaxf(sqrtf(ss), 1e-12f);
            float* dk = &Ks[rql * KS_STRIDE + sq * 12];
            dk[0] = tf32r(kpre[0].x*inv); dk[1] = tf32r(kpre[0].y*inv); dk[2]  = tf32r(kpre[0].z*inv); dk[3]  = tf32r(kpre[0].w*inv);
            dk[4] = tf32r(kpre[1].x*inv); dk[5] = tf32r(kpre[1].y*inv); dk[6]  = tf32r(kpre[1].z*inv); dk[7]  = tf32r(kpre[1].w*inv);
            dk[8] = tf32r(kpre[2].x*inv); dk[9] = tf32r(kpre[2].y*inv); dk[10] = tf32r(kpre[2].z*inv); dk[11] = tf32r(kpre[2].w*inv);
            float* dv = &Vs[rql * VS_STRIDE + sq * 12];
            dv[0] = tf32r(vpre[0].x); dv[1] = tf32r(vpre[0].y); dv[2]  = tf32r(vpre[0].z); dv[3]  = tf32r(vpre[0].w);
            dv[4] = tf32r(vpre[1].x); dv[5] = tf32r(vpre[1].y); dv[6]  = tf32r(vpre[1].z); dv[7]  = tf32r(vpre[1].w);
            dv[8] = tf32r(vpre[2].x); dv[9] = tf32r(vpre[2].y); dv[10] = tf32r(vpre[2].z); dv[11] = tf32r(vpre[2].w);
        }
        // issue next tile's loads; they complete under the mma phase
        if (kt < 15) {
            const int k1 = (kt + 1) * 64;
            const float* kp = kg + (size_t)(k1 + rql) * HD + sq * 12;
            const float* vp = vg + (size_t)(k1 + rql) * HD + sq * 12;
            kpre[0] = *(const float4*)(kp);     vpre[0] = *(const float4*)(vp);
            kpre[1] = *(const float4*)(kp + 4); vpre[1] = *(const float4*)(vp + 4);
            kpre[2] = *(const float4*)(kp + 8); vpre[2] = *(const float4*)(vp + 8);
        }
        __syncthreads();

        // ---- S = Q.K^T + softmax, two halves of 4 n-blocks ----
#pragma unroll
        for (int half = 0; half < 2; ++half) {
            float sacc[4][4];
#pragma unroll
            for (int i = 0; i < 4; ++i)
#pragma unroll
                for (int j = 0; j < 4; ++j) sacc[i][j] = 0.f;
#pragma unroll
            for (int nb4 = 0; nb4 < 4; ++nb4) {
                const int nb = half * 4 + nb4;
                const float* kbase = Ks + (nb * 8 + lr) * KS_STRIDE + lc;
#pragma unroll
                for (int kb = 0; kb < 6; ++kb) {
                    float b0 = kbase[kb * 8];
                    float b1 = kbase[kb * 8 + 4];
                    mma_tf32(sacc[nb4], qf[kb], b0, b1);
                }
            }
#pragma unroll
            for (int nb4 = 0; nb4 < 4; ++nb4) {
                const int nb = half * 4 + nb4;
                float p0 = __expf(fmaf(sacc[nb4][0], tpr, -mterm));
                float p1 = __expf(fmaf(sacc[nb4][1], tpr, -mterm));
                float p2 = __expf(fmaf(sacc[nb4][2], tpr, -mterm));
                float p3 = __expf(fmaf(sacc[nb4][3], tpr, -mterm));
                rsum0 += p0 + p1;
                rsum1 += p2 + p3;
                *(float2*)&Pw[lr * PS_STRIDE + nb * 8 + 2 * lc] =
                    make_float2(tf32r(p0), tf32r(p1));
                *(float2*)&Pw[(lr + 8) * PS_STRIDE + nb * 8 + 2 * lc] =
                    make_float2(tf32r(p2), tf32r(p3));
            }
        }
        __syncwarp();

        // ---- O += P.V ----
#pragma unroll
        for (int kb2 = 0; kb2 < 8; ++kb2) {
            float af[4];
            af[0] = Pw[lr * PS_STRIDE + kb2 * 8 + lc];
            af[1] = Pw[(lr + 8) * PS_STRIDE + kb2 * 8 + lc];
            af[2] = Pw[lr * PS_STRIDE + kb2 * 8 + lc + 4];
            af[3] = Pw[(lr + 8) * PS_STRIDE + kb2 * 8 + lc + 4];
            const float* vb0 = Vs + (kb2 * 8 + lc) * VS_STRIDE + lr;
            const float* vb1 = Vs + (kb2 * 8 + lc + 4) * VS_STRIDE + lr;
#pragma unroll
            for (int nb2 = 0; nb2 < 6; ++nb2) {
                mma_tf32(oacc[nb2], af, vb0[nb2 * 8], vb1[nb2 * 8]);
            }
        }
    }

    rsum0 += __shfl_xor_sync(0xffffffffu, rsum0, 1);
    rsum0 += __shfl_xor_sync(0xffffffffu, rsum0, 2);
    rsum1 += __shfl_xor_sync(0xffffffffu, rsum1, 1);
    rsum1 += __shfl_xor_sync(0xffffffffu, rsum1, 2);
    const float inv0 = 1.0f / rsum0;
    const float inv1 = 1.0f / rsum1;
    const int b = bh >> 3;
    const int row0 = i0 + w * 16 + lr;
    float* o0 = g_o + ((size_t)b * NN + row0) * CC + h * HD;
    float* o1 = o0 + 8 * CC;
#pragma unroll
    for (int nb = 0; nb < 6; ++nb) {
        *(float2*)&o0[nb * 8 + 2 * lc] = make_float2(oacc[nb][0] * inv0, oacc[nb][1] * inv0);
        *(float2*)&o1[nb * 8 + 2 * lc] = make_float2(oacc[nb][2] * inv1, oacc[nb][3] * inv1);
    }
}

// ===========================================================================
// GEMM 2 (tf32 TC): out[b,j,n] = sum_c g_o[b,n,c]*proj_w[j,c]+pb[j]
// R12 version (43us): 128x128 tile, register prefetch, (256,2).
// ===========================================================================
__global__ __launch_bounds__(256, 2) void gemm_proj_tc(const float* __restrict__ w,
                                                       const float* __restrict__ bias,
                                                       float* __restrict__ out) {
    __shared__ float Sm[9216];
    float* As = Sm;               // [m][k] 128x36
    float* Bs = Sm + 128 * 36;    // [j][k] 128x36
    float* Cs = Sm;               // [j][m] 64x132 per pass

    const int b  = blockIdx.z;
    const int m0 = blockIdx.y * 128;
    const int j0 = blockIdx.x * 128;
    const int t  = threadIdx.x;
    const int w8 = t >> 5, lane = t & 31;
    const int lr = lane >> 2, lc = lane & 3;
    const int wm = w8 & 1, wn = w8 >> 1;

    float acc[4][4][4];
#pragma unroll
    for (int i = 0; i < 4; ++i)
#pragma unroll
        for (int j = 0; j < 4; ++j)
#pragma unroll
            for (int e = 0; e < 4; ++e) acc[i][j][e] = 0.f;

    const float* A = g_o + (size_t)b * NN * CC;

    float4 apre[4], bpre[4];
#pragma unroll
    for (int r = 0; r < 4; ++r) {
        int idx = t + r * 256;
        int m = idx >> 3, k4 = idx & 7;
        apre[r] = *(const float4*)(A + (size_t)(m0 + m) * CC + k4 * 4);
        bpre[r] = *(const float4*)(w + (size_t)(j0 + m) * CC + k4 * 4);
    }

    for (int k0 = 0; k0 < CC; k0 += 32) {
        __syncthreads();
#pragma unroll
        for (int r = 0; r < 4; ++r) {
            int idx = t + r * 256;
            int m = idx >> 3, k4 = idx & 7;
            float4 v = apre[r];
            v.x = tf32r(v.x); v.y = tf32r(v.y); v.z = tf32r(v.z); v.w = tf32r(v.w);
            *(float4*)&As[m * 36 + k4 * 4] = v;
            float4 u = bpre[r];
            u.x = tf32r(u.x); u.y = tf32r(u.y); u.z = tf32r(u.z); u.w = tf32r(u.w);
            *(float4*)&Bs[m * 36 + k4 * 4] = u;
        }
        if (k0 + 32 < CC) {
            const int k1 = k0 + 32;
#pragma unroll
            for (int r = 0; r < 4; ++r) {
                int idx = t + r * 256;
                int m = idx >> 3, k4 = idx & 7;
                apre[r] = *(const float4*)(A + (size_t)(m0 + m) * CC + k1 + k4 * 4);
                bpre[r] = *(const float4*)(w + (size_t)(j0 + m) * CC + k1 + k4 * 4);
            }
        }
        __syncthreads();
#pragma unroll
        for (int kb = 0; kb < 4; ++kb) {
            float af[4][4], bf[4][2];
#pragma unroll
            for (int mt = 0; mt < 4; ++mt) {
                int base = (wm * 64 + mt * 16 + lr) * 36 + kb * 8 + lc;
                af[mt][0] = As[base];
                af[mt][1] = As[base + 8 * 36];
                af[mt][2] = As[base + 4];
                af[mt][3] = As[base + 8 * 36 + 4];
            }
#pragma unroll
            for (int nb = 0; nb < 4; ++nb) {
                int bb = (wn * 32 + nb * 8 + lr) * 36 + kb * 8 + lc;
                bf[nb][0] = Bs[bb];
                bf[nb][1] = Bs[bb + 4];
            }
#pragma unroll
            for (int mt = 0; mt < 4; ++mt)
#pragma unroll
                for (int nb = 0; nb < 4; ++nb)
                    mma_tf32(acc[mt][nb], af[mt], bf[nb][0], bf[nb][1]);
        }
    }

    // 2-pass epilogue: stage C[j][m] -> coalesced store along n
#pragma unroll
    for (int hh = 0; hh < 2; ++hh) {
        __syncthreads();
        if ((wn >> 1) == hh) {
#pragma unroll
            for (int mt = 0; mt < 4; ++mt) {
                int m1 = wm * 64 + mt * 16 + lr;
                int m2 = m1 + 8;
#pragma unroll
                for (int nb = 0; nb < 4; ++nb) {
                    int jl = (wn & 1) * 32 + nb * 8 + 2 * lc;
                    Cs[jl * 132 + m1]       = acc[mt][nb][0];
                    Cs[(jl + 1) * 132 + m1] = acc[mt][nb][1];
                    Cs[jl * 132 + m2]       = acc[mt][nb][2];
                    Cs[(jl + 1) * 132 + m2] = acc[mt][nb][3];
                }
            }
        }
        __syncthreads();
#pragma unroll
        for (int r = 0; r < 8; ++r) {
            int idx = t + r * 256;
            int jl = idx >> 5, m4 = idx & 31;
            int jg = j0 + hh * 64 + jl;
            float bj = bias[jg];
            float4 v = *(float4*)&Cs[jl * 132 + m4 * 4];
            v.x += bj; v.y += bj; v.z += bj; v.w += bj;
            *(float4*)(out + ((size_t)b * CC + jg) * NN + m0 + m4 * 4) = v;
        }
    }
}

// ===========================================================================
extern "C" void kernel_launch(void* const* d_in, const int* in_sizes, int n_in,
                              void* d_out, int out_size) {
    const float* x      = (const float*)d_in[0];
    const float* temp   = (const float*)d_in[1];
    const float* qkv_w  = (const float*)d_in[2];
    const float* qkv_b  = (const float*)d_in[3];
    const float* proj_w = (const float*)d_in[4];
    const float* proj_b = (const float*)d_in[5];
    float* out = (float*)d_out;

    static const int ATTN_SMEM = ATTN_SMEM_F * 4;   // 66560 bytes
    cudaFuncSetAttribute(attn_mma, cudaFuncAttributeMaxDynamicSharedMemorySize,
                         ATTN_SMEM);

    gemm_qkv_tc<<<dim3(9, 8, BB), 256>>>(x, qkv_w, qkv_b);
    attn_mma<<<dim3(8, BB * NH), 256, ATTN_SMEM>>>(temp);
    gemm_proj_tc<<<dim3(3, 8, BB), 256>>>(proj_w, proj_b, out);
}